// round 7
// baseline (speedup 1.0000x reference)
#include <cuda_runtime.h>
#include <cuda_bf16.h>
#include <cstdint>

// Problem constants: S=2048, B=32, D=256, H=4.  M = S*B = 65536 rows.
#define MROWS 65536
static constexpr size_t MD_ = 16777216ull;   // 65536*256

// Pool: 8 big fp32 buffers + 4M floats small/weight region (~560MB total)
__device__ float g_pool[8ull * 16777216ull + 4194304ull];

static constexpr size_t O_SMALL = 8ull * 16777216ull;
static constexpr size_t O_SSUM  = O_SMALL;
static constexpr size_t O_SSQ   = O_SMALL + 256;
static constexpr size_t O_SCALE = O_SMALL + 512;
static constexpr size_t O_SHIFT = O_SMALL + 768;
static constexpr size_t O_PM    = O_SMALL + 1024;
static constexpr size_t O_PZ    = O_PM + 16 * 32 * 256;
static constexpr size_t O_PA    = O_PZ + 16 * 32 * 256;
static constexpr size_t O_XCAT  = O_PA + 16 * 32 * 256;
static constexpr size_t O_H0    = O_XCAT + 32 * 1024;
static constexpr size_t O_H1    = O_H0 + 32 * 256;
static constexpr size_t O_WHI   = O_SMALL + 1048576;          // bf16 region (as floats)
static constexpr size_t O_WLO   = O_WHI + 655360;             // 1,310,720 bf16 each

// ---------------------------------------------------------------------------
// Warp-level HMMA helpers (base sm_80+ PTX — no "a"-gated features)
// ---------------------------------------------------------------------------
__device__ __forceinline__ uint32_t s2u(const void* p) {
    uint32_t a;
    asm("{ .reg .u64 t; cvta.to.shared.u64 t, %1; cvt.u32.u64 %0, t; }" : "=r"(a) : "l"(p));
    return a;
}
__device__ __forceinline__ void mma16816(float* d, const uint32_t* a, const uint32_t* b) {
    asm volatile(
        "mma.sync.aligned.m16n8k16.row.col.f32.bf16.bf16.f32 "
        "{%0,%1,%2,%3}, {%4,%5,%6,%7}, {%8,%9}, {%0,%1,%2,%3};"
        : "+f"(d[0]), "+f"(d[1]), "+f"(d[2]), "+f"(d[3])
        : "r"(a[0]), "r"(a[1]), "r"(a[2]), "r"(a[3]), "r"(b[0]), "r"(b[1]));
}
__device__ __forceinline__ void ldsm4(uint32_t* r, uint32_t a) {
    asm volatile("ldmatrix.sync.aligned.m8n8.x4.shared.b16 {%0,%1,%2,%3}, [%4];"
        : "=r"(r[0]), "=r"(r[1]), "=r"(r[2]), "=r"(r[3]) : "r"(a));
}
__device__ __forceinline__ void ldsm2(uint32_t* r, uint32_t a) {
    asm volatile("ldmatrix.sync.aligned.m8n8.x2.shared.b16 {%0,%1}, [%2];"
        : "=r"(r[0]), "=r"(r[1]) : "r"(a));
}
#define STS128(a, v)                                                            \
    asm volatile("st.shared.v4.b32 [%0], {%1,%2,%3,%4};"                        \
        :: "r"(a), "r"((v).x), "r"((v).y), "r"((v).z), "r"((v).w) : "memory")

// SMEM layout (bytes):
//   0     : ssum[256] (floats 0..255), ssq[256] (floats 256..511)
//   2048  : W stage0 { Whi 10240 | Wlo 10240 }, stage1 follows  (2 x 20480)
//   43008 : A_hi  128 rows x 264 b16 stride (67584 B)
//   110592: A_lo  (67584 B)
#define SM_WSTG   2048
#define WSTG_SZ   20480
#define W_LO_OFF  10240
#define SM_AHI    43008u
#define SM_ALO    110592u
#define ASTRIDE_B 528          // bytes per A smem row (264 bf16)
#define WSTRIDE_B 80           // bytes per W smem row (40 bf16)
#define GEMM_SMEM 178176

// ---------------------------------------------------------------------------
// HMMA GEMM: C[M,256] = act(A)[M,256] @ W[256,256]^T + bias
// act = relu(a*ascale + ashift) if ascale != nullptr.  W pre-split hi/lo bf16.
// Error-compensated: D += Ahi*Whi + Alo*Whi + Ahi*Wlo (fp32 accum in regs).
// A loaded once per 128-row block into persistent SMEM (hi/lo), reused by
// two N-passes of 128 cols each. Optional fused column stats (sum, sumsq).
// ---------------------------------------------------------------------------
__global__ __launch_bounds__(512)
void gemm_mma(const float* __restrict__ A,
              const __nv_bfloat16* __restrict__ Wh,
              const __nv_bfloat16* __restrict__ Wl,
              const float* __restrict__ bias,
              const float* __restrict__ ascale,
              const float* __restrict__ ashift,
              float* __restrict__ C,
              float* __restrict__ gsum, float* __restrict__ gsq)
{
    extern __shared__ __align__(16) char smem[];
    const uint32_t sb = s2u(smem);
    const int t = threadIdx.x, w = t >> 5, l = t & 31;
    const int wr = w >> 2, wc = w & 3;           // warp row/col within 128x128 pass tile
    const size_t r0 = (size_t)blockIdx.x * 128;
    const bool dostats = (gsum != nullptr);
    const bool bn = (ascale != nullptr);

    if (dostats) ((float*)smem)[t] = 0.f;        // zero ssum+ssq (512 floats)

    const int lrow = t >> 2;                     // 0..127 (loader row)
    const int lcol = (t & 3) * 8;                // 0,8,16,24 (loader k within chunk)

    // ldmatrix lane address components
    const int a_r = l & 15, a_k = (l >> 4) * 8;  // A: rows m0+a_r, k0+a_k
    const int b_r = l & 7,  b_k = ((l >> 3) & 1) * 8;

    float a_f[8];
    uint4 wh4, wl4;

    for (int nh = 0; nh < 2; nh++) {
        float acc[2][4][4];
#pragma unroll
        for (int mt = 0; mt < 2; mt++)
#pragma unroll
            for (int nt = 0; nt < 4; nt++)
#pragma unroll
                for (int j = 0; j < 4; j++) acc[mt][nt][j] = 0.f;

        // ---- prologue: fetch chunk 0 ----
        if (nh == 0) {
            const float4* p = (const float4*)(A + (r0 + lrow) * 256 + lcol);
            float4 v0 = p[0], v1 = p[1];
            a_f[0] = v0.x; a_f[1] = v0.y; a_f[2] = v0.z; a_f[3] = v0.w;
            a_f[4] = v1.x; a_f[5] = v1.y; a_f[6] = v1.z; a_f[7] = v1.w;
            if (bn) {
                float4 s0 = *(const float4*)(ascale + lcol);
                float4 s1 = *(const float4*)(ascale + lcol + 4);
                float4 h0 = *(const float4*)(ashift + lcol);
                float4 h1 = *(const float4*)(ashift + lcol + 4);
                a_f[0] = fmaxf(fmaf(a_f[0], s0.x, h0.x), 0.f);
                a_f[1] = fmaxf(fmaf(a_f[1], s0.y, h0.y), 0.f);
                a_f[2] = fmaxf(fmaf(a_f[2], s0.z, h0.z), 0.f);
                a_f[3] = fmaxf(fmaf(a_f[3], s0.w, h0.w), 0.f);
                a_f[4] = fmaxf(fmaf(a_f[4], s1.x, h1.x), 0.f);
                a_f[5] = fmaxf(fmaf(a_f[5], s1.y, h1.y), 0.f);
                a_f[6] = fmaxf(fmaf(a_f[6], s1.z, h1.z), 0.f);
                a_f[7] = fmaxf(fmaf(a_f[7], s1.w, h1.w), 0.f);
            }
        }
        {
            size_t widx = ((size_t)(nh * 128 + lrow)) * 256 + lcol;
            wh4 = *(const uint4*)(Wh + widx);
            wl4 = *(const uint4*)(Wl + widx);
        }
        if (nh == 1) __syncthreads();   // pass0 must be fully done before stage reuse

        // ---- STS chunk 0 ----
        if (nh == 0) {
            uint4 hv, lv;
            __nv_bfloat162* hp = (__nv_bfloat162*)&hv;
            __nv_bfloat162* lp = (__nv_bfloat162*)&lv;
#pragma unroll
            for (int i = 0; i < 4; i++) {
                __nv_bfloat16 h0 = __float2bfloat16(a_f[2 * i]);
                __nv_bfloat16 h1 = __float2bfloat16(a_f[2 * i + 1]);
                hp[i].x = h0; hp[i].y = h1;
                lp[i].x = __float2bfloat16(a_f[2 * i]     - __bfloat162float(h0));
                lp[i].y = __float2bfloat16(a_f[2 * i + 1] - __bfloat162float(h1));
            }
            uint32_t ao = (uint32_t)(lrow * ASTRIDE_B + lcol * 2);
            STS128(sb + SM_AHI + ao, hv);
            STS128(sb + SM_ALO + ao, lv);
        }
        {
            uint32_t wo = sb + SM_WSTG + (uint32_t)(lrow * WSTRIDE_B + lcol * 2);
            STS128(wo, wh4);
            STS128(wo + W_LO_OFF, wl4);
        }
        __syncthreads();

        // ---- K-chunk loop ----
        for (int c = 0; c < 8; c++) {
            const int s = c & 1;
            if (c < 7) {
                if (nh == 0) {
                    const float4* p = (const float4*)(A + (r0 + lrow) * 256 + (c + 1) * 32 + lcol);
                    float4 v0 = p[0], v1 = p[1];
                    a_f[0] = v0.x; a_f[1] = v0.y; a_f[2] = v0.z; a_f[3] = v0.w;
                    a_f[4] = v1.x; a_f[5] = v1.y; a_f[6] = v1.z; a_f[7] = v1.w;
                    if (bn) {
                        int kk = (c + 1) * 32 + lcol;
                        float4 s0 = *(const float4*)(ascale + kk);
                        float4 s1 = *(const float4*)(ascale + kk + 4);
                        float4 h0 = *(const float4*)(ashift + kk);
                        float4 h1 = *(const float4*)(ashift + kk + 4);
                        a_f[0] = fmaxf(fmaf(a_f[0], s0.x, h0.x), 0.f);
                        a_f[1] = fmaxf(fmaf(a_f[1], s0.y, h0.y), 0.f);
                        a_f[2] = fmaxf(fmaf(a_f[2], s0.z, h0.z), 0.f);
                        a_f[3] = fmaxf(fmaf(a_f[3], s0.w, h0.w), 0.f);
                        a_f[4] = fmaxf(fmaf(a_f[4], s1.x, h1.x), 0.f);
                        a_f[5] = fmaxf(fmaf(a_f[5], s1.y, h1.y), 0.f);
                        a_f[6] = fmaxf(fmaf(a_f[6], s1.z, h1.z), 0.f);
                        a_f[7] = fmaxf(fmaf(a_f[7], s1.w, h1.w), 0.f);
                    }
                }
                size_t widx = ((size_t)(nh * 128 + lrow)) * 256 + (c + 1) * 32 + lcol;
                wh4 = *(const uint4*)(Wh + widx);
                wl4 = *(const uint4*)(Wl + widx);
            }

            // ---- MMA on chunk c ----
            const uint32_t stgW = sb + SM_WSTG + (uint32_t)s * WSTG_SZ;
#pragma unroll
            for (int ks = 0; ks < 2; ks++) {
                const int k0 = c * 32 + ks * 16;       // global k (A smem)
                uint32_t ah[2][4], al[2][4], bb[4][2];
#pragma unroll
                for (int mt = 0; mt < 2; mt++)
                    ldsm4(ah[mt], sb + SM_AHI +
                          (uint32_t)((wr * 32 + mt * 16 + a_r) * ASTRIDE_B + (k0 + a_k) * 2));
#pragma unroll
                for (int nt = 0; nt < 4; nt++)
                    ldsm2(bb[nt], stgW +
                          (uint32_t)((wc * 32 + nt * 8 + b_r) * WSTRIDE_B + (ks * 16 + b_k) * 2));
#pragma unroll
                for (int mt = 0; mt < 2; mt++)
#pragma unroll
                    for (int nt = 0; nt < 4; nt++)
                        mma16816(acc[mt][nt], ah[mt], bb[nt]);
#pragma unroll
                for (int mt = 0; mt < 2; mt++)
                    ldsm4(al[mt], sb + SM_ALO +
                          (uint32_t)((wr * 32 + mt * 16 + a_r) * ASTRIDE_B + (k0 + a_k) * 2));
#pragma unroll
                for (int mt = 0; mt < 2; mt++)
#pragma unroll
                    for (int nt = 0; nt < 4; nt++)
                        mma16816(acc[mt][nt], al[mt], bb[nt]);
#pragma unroll
                for (int nt = 0; nt < 4; nt++)
                    ldsm2(bb[nt], stgW + W_LO_OFF +
                          (uint32_t)((wc * 32 + nt * 8 + b_r) * WSTRIDE_B + (ks * 16 + b_k) * 2));
#pragma unroll
                for (int mt = 0; mt < 2; mt++)
#pragma unroll
                    for (int nt = 0; nt < 4; nt++)
                        mma16816(acc[mt][nt], ah[mt], bb[nt]);
            }

            if (c < 7) {
                __syncthreads();
                if (nh == 0) {
                    uint4 hv, lv;
                    __nv_bfloat162* hp = (__nv_bfloat162*)&hv;
                    __nv_bfloat162* lp = (__nv_bfloat162*)&lv;
#pragma unroll
                    for (int i = 0; i < 4; i++) {
                        __nv_bfloat16 h0 = __float2bfloat16(a_f[2 * i]);
                        __nv_bfloat16 h1 = __float2bfloat16(a_f[2 * i + 1]);
                        hp[i].x = h0; hp[i].y = h1;
                        lp[i].x = __float2bfloat16(a_f[2 * i]     - __bfloat162float(h0));
                        lp[i].y = __float2bfloat16(a_f[2 * i + 1] - __bfloat162float(h1));
                    }
                    uint32_t ao = (uint32_t)(lrow * ASTRIDE_B + ((c + 1) * 32 + lcol) * 2);
                    STS128(sb + SM_AHI + ao, hv);
                    STS128(sb + SM_ALO + ao, lv);
                }
                uint32_t wo = sb + SM_WSTG + (uint32_t)(s ^ 1) * WSTG_SZ +
                              (uint32_t)(lrow * WSTRIDE_B + lcol * 2);
                STS128(wo, wh4);
                STS128(wo + W_LO_OFF, wl4);
                __syncthreads();
            }
        }

        // ---- epilogue for this N-pass ----
        const int erow = wr * 32 + (l >> 2);
#pragma unroll
        for (int mt = 0; mt < 2; mt++) {
            const size_t row = r0 + erow + mt * 16;
#pragma unroll
            for (int nt = 0; nt < 4; nt++) {
                const int col = nh * 128 + wc * 32 + nt * 8 + (l & 3) * 2;
                float2 bb2 = *(const float2*)(bias + col);
                float v0 = acc[mt][nt][0] + bb2.x;
                float v1 = acc[mt][nt][1] + bb2.y;
                float v2 = acc[mt][nt][2] + bb2.x;
                float v3 = acc[mt][nt][3] + bb2.y;
                *(float2*)(C + row * 256 + col)       = make_float2(v0, v1);
                *(float2*)(C + (row + 8) * 256 + col) = make_float2(v2, v3);
                if (dostats) {
                    float* ss = (float*)smem;
                    atomicAdd(ss + col,           v0 + v2);
                    atomicAdd(ss + col + 1,       v1 + v3);
                    atomicAdd(ss + 256 + col,     v0 * v0 + v2 * v2);
                    atomicAdd(ss + 256 + col + 1, v1 * v1 + v3 * v3);
                }
            }
        }
    }

    if (dostats) {
        __syncthreads();
        if (t < 256) {
            atomicAdd(gsum + t, ((float*)smem)[t]);
            atomicAdd(gsq  + t, ((float*)smem)[256 + t]);
        }
    }
}

// ---------------------------------------------------------------------------
// Weight split: fp32 -> bf16 hi + bf16 residual lo, for 5 weight arrays x 4 heads
// ---------------------------------------------------------------------------
__global__ void wsplit(const float* __restrict__ w0, const float* __restrict__ w1,
                       const float* __restrict__ w2, const float* __restrict__ w3,
                       const float* __restrict__ w4,
                       __nv_bfloat16* __restrict__ hi, __nv_bfloat16* __restrict__ lo)
{
    size_t i = (size_t)blockIdx.x * 256 + threadIdx.x;   // < 1,310,720
    size_t a = i >> 18, r = i & 262143;
    const float* s = (a == 0) ? w0 : (a == 1) ? w1 : (a == 2) ? w2 : (a == 3) ? w3 : w4;
    float x = s[r];
    __nv_bfloat16 h = __float2bfloat16(x);
    hi[i] = h;
    lo[i] = __float2bfloat16(x - __bfloat162float(h));
}

// W = K - Q, fused per-channel stats
__global__ void subk_stats(const float* __restrict__ K, const float* __restrict__ Q,
                           float* __restrict__ W, float* __restrict__ gsum,
                           float* __restrict__ gsq)
{
    int col = threadIdx.x;
    size_t base = (size_t)blockIdx.x * 128 * 256 + col;
    float a = 0.f, b = 0.f;
#pragma unroll 4
    for (int i = 0; i < 128; i++) {
        size_t idx = base + (size_t)i * 256;
        float w = K[idx] - Q[idx];
        W[idx] = w;
        a += w;
        b = fmaf(w, w, b);
    }
    atomicAdd(&gsum[col], a);
    atomicAdd(&gsq[col], b);
}

__global__ void zerok(float* a, float* b)
{
    a[threadIdx.x] = 0.f;
    b[threadIdx.x] = 0.f;
}

__global__ void bnfinal(const float* __restrict__ s, const float* __restrict__ sq,
                        const float* __restrict__ gamma, const float* __restrict__ beta,
                        float* __restrict__ scale, float* __restrict__ shift)
{
    int c = threadIdx.x;
    const float inv = 1.f / 65536.f;
    float m = s[c] * inv;
    float v = sq[c] * inv - m * m;
    float r = rsqrtf(v + 1e-5f);
    float sc = r * gamma[c];
    scale[c] = sc;
    shift[c] = beta[c] - m * sc;
}

// Online softmax over S fused with weighted V-sum (16-way split over S)
__global__ void smax_part(const float* __restrict__ W3, const float* __restrict__ V,
                          float* __restrict__ pm, float* __restrict__ pz,
                          float* __restrict__ pa)
{
    int b = blockIdx.x, ch = blockIdx.y, d = threadIdx.x;
    float m = -1e30f, Z = 0.f, acc = 0.f;
#pragma unroll 4
    for (int j = 0; j < 128; j++) {
        int s_ = ch * 128 + j;
        size_t idx = ((size_t)(s_ * 32 + b)) * 256 + d;
        float w = W3[idx];
        float v = V[idx];
        float nm = fmaxf(m, w);
        float e0 = __expf(m - nm);
        float e1 = __expf(w - nm);
        Z = Z * e0 + e1;
        acc = fmaf(v, e1, acc * e0);
        m = nm;
    }
    int o = (ch * 32 + b) * 256 + d;
    pm[o] = m; pz[o] = Z; pa[o] = acc;
}

__global__ void smax_comb(const float* __restrict__ pm, const float* __restrict__ pz,
                          const float* __restrict__ pa, float* __restrict__ xcat,
                          int head)
{
    int b = blockIdx.x, d = threadIdx.x;
    float m = -1e30f, Z = 0.f, acc = 0.f;
#pragma unroll
    for (int ch = 0; ch < 16; ch++) {
        int o = (ch * 32 + b) * 256 + d;
        float cm = pm[o];
        float nm = fmaxf(m, cm);
        float e0 = __expf(m - nm);
        float e1 = __expf(cm - nm);
        Z = Z * e0 + pz[o] * e1;
        acc = acc * e0 + pa[o] * e1;
        m = nm;
    }
    xcat[b * 1024 + head * 256 + d] = acc / Z;
}

__global__ void mlp_k(const float* __restrict__ X, const float* __restrict__ Wm,
                      const float* __restrict__ bias, float* __restrict__ Y,
                      int Kdim, int do_relu)
{
    __shared__ float sx[1024];
    int b = blockIdx.x, c = threadIdx.x;
    for (int t = c; t < Kdim; t += 256) sx[t] = X[b * Kdim + t];
    __syncthreads();
    float s = 0.f;
#pragma unroll 4
    for (int t = 0; t < Kdim; t++) s = fmaf(sx[t], Wm[c * Kdim + t], s);
    s += bias[c];
    if (do_relu) s = fmaxf(s, 0.f);
    Y[b * 256 + c] = s;
}

// ---------------------------------------------------------------------------
extern "C" void kernel_launch(void* const* d_in, const int* in_sizes, int n_in,
                              void* d_out, int out_size)
{
    float* pool = nullptr;
    cudaGetSymbolAddress((void**)&pool, g_pool);

    cudaFuncSetAttribute(gemm_mma, cudaFuncAttributeMaxDynamicSharedMemorySize, GEMM_SMEM);

    const float* q   = (const float*)d_in[0];
    const float* k   = (const float*)d_in[1];
    const float* v   = (const float*)d_in[2];
    const float* wq  = (const float*)d_in[3];
    const float* bq  = (const float*)d_in[4];
    const float* wk  = (const float*)d_in[5];
    const float* bk  = (const float*)d_in[6];
    const float* wv  = (const float*)d_in[7];
    const float* bv  = (const float*)d_in[8];
    const float* g1  = (const float*)d_in[9];
    const float* be1 = (const float*)d_in[10];
    const float* wl1 = (const float*)d_in[11];
    const float* bl1 = (const float*)d_in[12];
    const float* g2  = (const float*)d_in[13];
    const float* be2 = (const float*)d_in[14];
    const float* wl2 = (const float*)d_in[15];
    const float* bl2 = (const float*)d_in[16];
    const float* mw0 = (const float*)d_in[17];
    const float* mb0 = (const float*)d_in[18];
    const float* mw1 = (const float*)d_in[19];
    const float* mb1 = (const float*)d_in[20];
    const float* mw2 = (const float*)d_in[21];
    const float* mb2 = (const float*)d_in[22];

    float* Qb[2] = {pool + 0 * MD_, pool + 1 * MD_};
    float* Kb[2] = {pool + 2 * MD_, pool + 3 * MD_};
    float* Vb[2] = {pool + 4 * MD_, pool + 5 * MD_};
    float* W     = pool + 6 * MD_;
    float* W2    = pool + 7 * MD_;
    float* ssum  = pool + O_SSUM;
    float* ssq   = pool + O_SSQ;
    float* scale = pool + O_SCALE;
    float* shift = pool + O_SHIFT;
    float* pm    = pool + O_PM;
    float* pz    = pool + O_PZ;
    float* pa    = pool + O_PA;
    float* xcat  = pool + O_XCAT;
    float* h0    = pool + O_H0;
    float* h1    = pool + O_H1;
    __nv_bfloat16* whi = (__nv_bfloat16*)(pool + O_WHI);
    __nv_bfloat16* wlo = (__nv_bfloat16*)(pool + O_WLO);

    // split all 20 weight matrices to bf16 hi/lo  (arr order: wq,wk,wv,wl1,wl2)
    wsplit<<<5120, 256>>>(wq, wk, wv, wl1, wl2, whi, wlo);

    for (int i = 0; i < 4; i++) {
        const float* Qs = i ? Qb[(i - 1) & 1] : q;
        const float* Ks = i ? Kb[(i - 1) & 1] : k;
        const float* Vs = i ? Vb[(i - 1) & 1] : v;
        float* Qd = Qb[i & 1];
        float* Kd = Kb[i & 1];
        float* Vd = Vb[i & 1];

        const __nv_bfloat16* whq  = whi + (0 * 4 + i) * 65536;
        const __nv_bfloat16* wlq  = wlo + (0 * 4 + i) * 65536;
        const __nv_bfloat16* whk  = whi + (1 * 4 + i) * 65536;
        const __nv_bfloat16* wlk  = wlo + (1 * 4 + i) * 65536;
        const __nv_bfloat16* whv  = whi + (2 * 4 + i) * 65536;
        const __nv_bfloat16* wlv  = wlo + (2 * 4 + i) * 65536;
        const __nv_bfloat16* wh1  = whi + (3 * 4 + i) * 65536;
        const __nv_bfloat16* wl1s = wlo + (3 * 4 + i) * 65536;
        const __nv_bfloat16* wh2  = whi + (4 * 4 + i) * 65536;
        const __nv_bfloat16* wl2s = wlo + (4 * 4 + i) * 65536;

        gemm_mma<<<512, 512, GEMM_SMEM>>>(Qs, whq, wlq, bq + i * 256,
                                          nullptr, nullptr, Qd, nullptr, nullptr);
        gemm_mma<<<512, 512, GEMM_SMEM>>>(Ks, whk, wlk, bk + i * 256,
                                          nullptr, nullptr, Kd, nullptr, nullptr);
        gemm_mma<<<512, 512, GEMM_SMEM>>>(Vs, whv, wlv, bv + i * 256,
                                          nullptr, nullptr, Vd, nullptr, nullptr);

        zerok<<<1, 256>>>(ssum, ssq);
        subk_stats<<<512, 256>>>(Kd, Qd, W, ssum, ssq);
        bnfinal<<<1, 256>>>(ssum, ssq, g1 + i * 256, be1 + i * 256, scale, shift);

        zerok<<<1, 256>>>(ssum, ssq);
        gemm_mma<<<512, 512, GEMM_SMEM>>>(W, wh1, wl1s, bl1 + i * 256,
                                          scale, shift, W2, ssum, ssq);
        bnfinal<<<1, 256>>>(ssum, ssq, g2 + i * 256, be2 + i * 256, scale, shift);

        gemm_mma<<<512, 512, GEMM_SMEM>>>(W2, wh2, wl2s, bl2 + i * 256,
                                          scale, shift, W, nullptr, nullptr);

        smax_part<<<dim3(32, 16), 256>>>(W, Vd, pm, pz, pa);
        smax_comb<<<32, 256>>>(pm, pz, pa, xcat, i);
    }

    mlp_k<<<32, 256>>>(xcat, mw0, mb0, h0, 1024, 1);
    mlp_k<<<32, 256>>>(h0, mw1, mb1, h1, 256, 1);
    mlp_k<<<32, 256>>>(h1, mw2, mb2, (float*)d_out, 256, 0);
}

// round 8
// speedup vs baseline: 2.0135x; 2.0135x over previous
#include <cuda_runtime.h>
#include <cuda_bf16.h>
#include <cstdint>

// Problem constants: S=2048, B=32, D=256, H=4.  M = S*B = 65536 rows.
#define MROWS 65536
static constexpr size_t MD_ = 16777216ull;   // 65536*256

// Pool: 8 big fp32 buffers + 4M floats small/weight region (~560MB total)
__device__ float g_pool[8ull * 16777216ull + 4194304ull];

static constexpr size_t O_SMALL = 8ull * 16777216ull;
static constexpr size_t O_SSUM  = O_SMALL;
static constexpr size_t O_SSQ   = O_SMALL + 256;
static constexpr size_t O_SCALE = O_SMALL + 512;
static constexpr size_t O_SHIFT = O_SMALL + 768;
static constexpr size_t O_PM    = O_SMALL + 1024;
static constexpr size_t O_PZ    = O_PM + 16 * 32 * 256;
static constexpr size_t O_PA    = O_PZ + 16 * 32 * 256;
static constexpr size_t O_XCAT  = O_PA + 16 * 32 * 256;
static constexpr size_t O_H0    = O_XCAT + 32 * 1024;
static constexpr size_t O_H1    = O_H0 + 32 * 256;
static constexpr size_t O_WHI   = O_SMALL + 1048576;          // bf16 region (as floats)
static constexpr size_t O_WLO   = O_WHI + 655360;             // 1,310,720 bf16 each

// ---------------------------------------------------------------------------
// Warp-level HMMA helpers (base sm_80+ PTX — no "a"-gated features)
// ---------------------------------------------------------------------------
__device__ __forceinline__ uint32_t s2u(const void* p) {
    uint32_t a;
    asm("{ .reg .u64 t; cvta.to.shared.u64 t, %1; cvt.u32.u64 %0, t; }" : "=r"(a) : "l"(p));
    return a;
}
__device__ __forceinline__ void mma16816(float* d, const uint32_t* a, const uint32_t* b) {
    asm volatile(
        "mma.sync.aligned.m16n8k16.row.col.f32.bf16.bf16.f32 "
        "{%0,%1,%2,%3}, {%4,%5,%6,%7}, {%8,%9}, {%0,%1,%2,%3};"
        : "+f"(d[0]), "+f"(d[1]), "+f"(d[2]), "+f"(d[3])
        : "r"(a[0]), "r"(a[1]), "r"(a[2]), "r"(a[3]), "r"(b[0]), "r"(b[1]));
}
__device__ __forceinline__ void ldsm4(uint32_t* r, uint32_t a) {
    asm volatile("ldmatrix.sync.aligned.m8n8.x4.shared.b16 {%0,%1,%2,%3}, [%4];"
        : "=r"(r[0]), "=r"(r[1]), "=r"(r[2]), "=r"(r[3]) : "r"(a));
}
__device__ __forceinline__ void cpasync16(uint32_t dst, const void* src) {
    asm volatile("cp.async.cg.shared.global [%0], [%1], 16;" :: "r"(dst), "l"(src));
}
__device__ __forceinline__ void cpcommit() { asm volatile("cp.async.commit_group;"); }
__device__ __forceinline__ void cpwait0()  { asm volatile("cp.async.wait_group 0;" ::: "memory"); }
#define STS128(a, v)                                                            \
    asm volatile("st.shared.v4.b32 [%0], {%1,%2,%3,%4};"                        \
        :: "r"(a), "r"((v).x), "r"((v).y), "r"((v).z), "r"((v).w) : "memory")

// SMEM layout (bytes):
//   0    : ssum[256] floats, ssq[256] floats (stats scratch)
//   2048 : stage0 { A_hi 8KB | A_lo 8KB | W_hi 16KB | W_lo 16KB } = 48KB
//   51200: stage1 (48KB)
// rows are 64B (32 bf16); 16B granule swizzle: g' = g ^ ((row>>1)&3)
#define STG_ALO   8192u
#define STG_WHI   16384u
#define STG_WLO   32768u
#define STG_SIZE  49152u
#define GEMM_SMEM (2048 + 2 * 49152)       // 100352 bytes

// ---------------------------------------------------------------------------
// HMMA GEMM: C[M,256] = act(A)[M,256] @ W[256,256]^T + bias
// act = relu(a*ascale + ashift) if ascale != nullptr.  W pre-split hi/lo bf16.
// Error-compensated: D += Ahi*Whi + Alo*Whi + Ahi*Wlo (fp32 accum in regs).
// Single N=256 pass, 16 warps (4x4), warp tile 32x64, cp.async W pipeline,
// one barrier per 32-k chunk. Optional fused column stats (sum, sumsq).
// ---------------------------------------------------------------------------
__global__ __launch_bounds__(512)
void gemm_mma(const float* __restrict__ A,
              const __nv_bfloat16* __restrict__ Wh,
              const __nv_bfloat16* __restrict__ Wl,
              const float* __restrict__ bias,
              const float* __restrict__ ascale,
              const float* __restrict__ ashift,
              float* __restrict__ C,
              float* __restrict__ gsum, float* __restrict__ gsq)
{
    extern __shared__ __align__(16) char smem[];
    const uint32_t sb = s2u(smem);
    const int t = threadIdx.x, w = t >> 5, l = t & 31;
    const int wr = w >> 2, wc = w & 3;           // 4x4 warp grid; warp tile 32x64
    const size_t r0 = (size_t)blockIdx.x * 128;
    const bool dostats = (gsum != nullptr);
    const bool bn = (ascale != nullptr);

    ((float*)smem)[t] = 0.f;                     // zero 512 stats floats (t<512)

    const uint32_t stg0 = sb + 2048;

    // ---- loader thread mapping ----
    const int arow = t >> 2, ag = t & 3;         // A: 128 rows x 4 granules
    const uint32_t a_sts = (uint32_t)(arow * 64 + ((ag ^ ((arow >> 1) & 3)) << 4));
    const int wrow = t >> 2, wg = t & 3;         // W: rows {wrow, wrow+128}
    const uint32_t w_sts = (uint32_t)(wrow * 64 + ((wg ^ ((wrow >> 1) & 3)) << 4));

    // ---- ldmatrix lane constants ----
    const int a_base_row = wr * 32 + (l & 15);
    const int sa = (a_base_row >> 1) & 3;
    const uint32_t a_off0 = (uint32_t)(a_base_row * 64);
    const int b_base_row = wc * 64 + ((l >> 4) << 3) + (l & 7);
    const int sbz = (b_base_row >> 1) & 3;
    const uint32_t b_off0 = (uint32_t)(b_base_row * 64);
    const int a_gl = l >> 4;                     // A granule low bit source
    const int b_gl = (l >> 3) & 1;

    float acc[2][8][4];
#pragma unroll
    for (int mt = 0; mt < 2; mt++)
#pragma unroll
        for (int nt = 0; nt < 8; nt++)
#pragma unroll
            for (int j = 0; j < 4; j++) acc[mt][nt][j] = 0.f;

    float af[8];

    // ===== prologue: chunk 0 =====
    {
        const float4* p = (const float4*)(A + (r0 + arow) * 256 + ag * 8);
        float4 v0 = p[0], v1 = p[1];
        af[0] = v0.x; af[1] = v0.y; af[2] = v0.z; af[3] = v0.w;
        af[4] = v1.x; af[5] = v1.y; af[6] = v1.z; af[7] = v1.w;
        if (bn) {
            int kk = ag * 8;
#pragma unroll
            for (int i = 0; i < 8; i++)
                af[i] = fmaxf(fmaf(af[i], ascale[kk + i], ashift[kk + i]), 0.f);
        }
        size_t ws = (size_t)wrow * 256 + wg * 8;
        cpasync16(stg0 + STG_WHI + w_sts,        Wh + ws);
        cpasync16(stg0 + STG_WHI + w_sts + 8192, Wh + ws + 128 * 256);
        cpasync16(stg0 + STG_WLO + w_sts,        Wl + ws);
        cpasync16(stg0 + STG_WLO + w_sts + 8192, Wl + ws + 128 * 256);
        cpcommit();
        // split A -> STS
        uint4 hv, lv;
        __nv_bfloat162* hp = (__nv_bfloat162*)&hv;
        __nv_bfloat162* lp = (__nv_bfloat162*)&lv;
#pragma unroll
        for (int i = 0; i < 4; i++) {
            __nv_bfloat16 h0 = __float2bfloat16(af[2 * i]);
            __nv_bfloat16 h1 = __float2bfloat16(af[2 * i + 1]);
            hp[i].x = h0; hp[i].y = h1;
            lp[i].x = __float2bfloat16(af[2 * i]     - __bfloat162float(h0));
            lp[i].y = __float2bfloat16(af[2 * i + 1] - __bfloat162float(h1));
        }
        STS128(stg0 + a_sts, hv);
        STS128(stg0 + STG_ALO + a_sts, lv);
        cpwait0();
    }
    __syncthreads();

    // ===== mainloop: 8 chunks of k32 =====
    for (int c = 0; c < 8; c++) {
        const uint32_t stgs = stg0 + (uint32_t)(c & 1) * STG_SIZE;
        const uint32_t stgn = stg0 + (uint32_t)((c + 1) & 1) * STG_SIZE;

        if (c < 7) {
            const float4* p = (const float4*)(A + (r0 + arow) * 256 + (c + 1) * 32 + ag * 8);
            float4 v0 = p[0], v1 = p[1];
            af[0] = v0.x; af[1] = v0.y; af[2] = v0.z; af[3] = v0.w;
            af[4] = v1.x; af[5] = v1.y; af[6] = v1.z; af[7] = v1.w;
            if (bn) {
                int kk = (c + 1) * 32 + ag * 8;
#pragma unroll
                for (int i = 0; i < 8; i++)
                    af[i] = fmaxf(fmaf(af[i], ascale[kk + i], ashift[kk + i]), 0.f);
            }
            size_t ws = (size_t)wrow * 256 + (c + 1) * 32 + wg * 8;
            cpasync16(stgn + STG_WHI + w_sts,        Wh + ws);
            cpasync16(stgn + STG_WHI + w_sts + 8192, Wh + ws + 128 * 256);
            cpasync16(stgn + STG_WLO + w_sts,        Wl + ws);
            cpasync16(stgn + STG_WLO + w_sts + 8192, Wl + ws + 128 * 256);
            cpcommit();
        }

        // ---- compute chunk c ----
#pragma unroll
        for (int ks = 0; ks < 2; ks++) {
            uint32_t ah[2][4], al[2][4], bb[4];
            const uint32_t agoff = (uint32_t)(((ks * 2 + a_gl) ^ sa) << 4);
            ldsm4(ah[0], stgs + a_off0 + agoff);
            ldsm4(ah[1], stgs + a_off0 + 1024 + agoff);
            ldsm4(al[0], stgs + STG_ALO + a_off0 + agoff);
            ldsm4(al[1], stgs + STG_ALO + a_off0 + 1024 + agoff);
            const uint32_t bgoff = (uint32_t)(((ks * 2 + b_gl) ^ sbz) << 4);
#pragma unroll
            for (int n2 = 0; n2 < 4; n2++) {
                const uint32_t brow = b_off0 + (uint32_t)(n2 * 1024);
                ldsm4(bb, stgs + STG_WHI + brow + bgoff);
                mma16816(acc[0][n2 * 2],     ah[0], bb);
                mma16816(acc[0][n2 * 2 + 1], ah[0], bb + 2);
                mma16816(acc[1][n2 * 2],     ah[1], bb);
                mma16816(acc[1][n2 * 2 + 1], ah[1], bb + 2);
                mma16816(acc[0][n2 * 2],     al[0], bb);
                mma16816(acc[0][n2 * 2 + 1], al[0], bb + 2);
                mma16816(acc[1][n2 * 2],     al[1], bb);
                mma16816(acc[1][n2 * 2 + 1], al[1], bb + 2);
                ldsm4(bb, stgs + STG_WLO + brow + bgoff);
                mma16816(acc[0][n2 * 2],     ah[0], bb);
                mma16816(acc[0][n2 * 2 + 1], ah[0], bb + 2);
                mma16816(acc[1][n2 * 2],     ah[1], bb);
                mma16816(acc[1][n2 * 2 + 1], ah[1], bb + 2);
            }
        }

        if (c < 7) {
            uint4 hv, lv;
            __nv_bfloat162* hp = (__nv_bfloat162*)&hv;
            __nv_bfloat162* lp = (__nv_bfloat162*)&lv;
#pragma unroll
            for (int i = 0; i < 4; i++) {
                __nv_bfloat16 h0 = __float2bfloat16(af[2 * i]);
                __nv_bfloat16 h1 = __float2bfloat16(af[2 * i + 1]);
                hp[i].x = h0; hp[i].y = h1;
                lp[i].x = __float2bfloat16(af[2 * i]     - __bfloat162float(h0));
                lp[i].y = __float2bfloat16(af[2 * i + 1] - __bfloat162float(h1));
            }
            STS128(stgn + a_sts, hv);
            STS128(stgn + STG_ALO + a_sts, lv);
            cpwait0();
            __syncthreads();
        }
    }

    // ===== epilogue =====
    const int erow = wr * 32 + (l >> 2);
#pragma unroll
    for (int nt = 0; nt < 8; nt++) {
        const int col = wc * 64 + nt * 8 + (l & 3) * 2;
        const float2 bb2 = *(const float2*)(bias + col);
        float s0 = 0.f, s1 = 0.f, q0 = 0.f, q1 = 0.f;
#pragma unroll
        for (int mt = 0; mt < 2; mt++) {
            const size_t row = r0 + erow + mt * 16;
            float v0 = acc[mt][nt][0] + bb2.x;
            float v1 = acc[mt][nt][1] + bb2.y;
            float v2 = acc[mt][nt][2] + bb2.x;
            float v3 = acc[mt][nt][3] + bb2.y;
            *(float2*)(C + row * 256 + col)       = make_float2(v0, v1);
            *(float2*)(C + (row + 8) * 256 + col) = make_float2(v2, v3);
            s0 += v0 + v2; s1 += v1 + v3;
            q0 += v0 * v0 + v2 * v2; q1 += v1 * v1 + v3 * v3;
        }
        if (dostats) {
            float* ss = (float*)smem;
            atomicAdd(ss + col,           s0);
            atomicAdd(ss + col + 1,       s1);
            atomicAdd(ss + 256 + col,     q0);
            atomicAdd(ss + 256 + col + 1, q1);
        }
    }

    if (dostats) {
        __syncthreads();
        if (t < 256) {
            atomicAdd(gsum + t, ((float*)smem)[t]);
            atomicAdd(gsq  + t, ((float*)smem)[256 + t]);
        }
    }
}

// ---------------------------------------------------------------------------
// Weight split: fp32 -> bf16 hi + bf16 residual lo, for 5 weight arrays x 4 heads
// ---------------------------------------------------------------------------
__global__ void wsplit(const float* __restrict__ w0, const float* __restrict__ w1,
                       const float* __restrict__ w2, const float* __restrict__ w3,
                       const float* __restrict__ w4,
                       __nv_bfloat16* __restrict__ hi, __nv_bfloat16* __restrict__ lo)
{
    size_t i = (size_t)blockIdx.x * 256 + threadIdx.x;   // < 1,310,720
    size_t a = i >> 18, r = i & 262143;
    const float* s = (a == 0) ? w0 : (a == 1) ? w1 : (a == 2) ? w2 : (a == 3) ? w3 : w4;
    float x = s[r];
    __nv_bfloat16 h = __float2bfloat16(x);
    hi[i] = h;
    lo[i] = __float2bfloat16(x - __bfloat162float(h));
}

// W = K - Q, fused per-channel stats
__global__ void subk_stats(const float* __restrict__ K, const float* __restrict__ Q,
                           float* __restrict__ W, float* __restrict__ gsum,
                           float* __restrict__ gsq)
{
    int col = threadIdx.x;
    size_t base = (size_t)blockIdx.x * 128 * 256 + col;
    float a = 0.f, b = 0.f;
#pragma unroll 4
    for (int i = 0; i < 128; i++) {
        size_t idx = base + (size_t)i * 256;
        float w = K[idx] - Q[idx];
        W[idx] = w;
        a += w;
        b = fmaf(w, w, b);
    }
    atomicAdd(&gsum[col], a);
    atomicAdd(&gsq[col], b);
}

__global__ void zerok(float* a, float* b)
{
    a[threadIdx.x] = 0.f;
    b[threadIdx.x] = 0.f;
}

__global__ void bnfinal(const float* __restrict__ s, const float* __restrict__ sq,
                        const float* __restrict__ gamma, const float* __restrict__ beta,
                        float* __restrict__ scale, float* __restrict__ shift)
{
    int c = threadIdx.x;
    const float inv = 1.f / 65536.f;
    float m = s[c] * inv;
    float v = sq[c] * inv - m * m;
    float r = rsqrtf(v + 1e-5f);
    float sc = r * gamma[c];
    scale[c] = sc;
    shift[c] = beta[c] - m * sc;
}

// Online softmax over S fused with weighted V-sum (16-way split over S)
__global__ void smax_part(const float* __restrict__ W3, const float* __restrict__ V,
                          float* __restrict__ pm, float* __restrict__ pz,
                          float* __restrict__ pa)
{
    int b = blockIdx.x, ch = blockIdx.y, d = threadIdx.x;
    float m = -1e30f, Z = 0.f, acc = 0.f;
#pragma unroll 4
    for (int j = 0; j < 128; j++) {
        int s_ = ch * 128 + j;
        size_t idx = ((size_t)(s_ * 32 + b)) * 256 + d;
        float w = W3[idx];
        float v = V[idx];
        float nm = fmaxf(m, w);
        float e0 = __expf(m - nm);
        float e1 = __expf(w - nm);
        Z = Z * e0 + e1;
        acc = fmaf(v, e1, acc * e0);
        m = nm;
    }
    int o = (ch * 32 + b) * 256 + d;
    pm[o] = m; pz[o] = Z; pa[o] = acc;
}

__global__ void smax_comb(const float* __restrict__ pm, const float* __restrict__ pz,
                          const float* __restrict__ pa, float* __restrict__ xcat,
                          int head)
{
    int b = blockIdx.x, d = threadIdx.x;
    float m = -1e30f, Z = 0.f, acc = 0.f;
#pragma unroll
    for (int ch = 0; ch < 16; ch++) {
        int o = (ch * 32 + b) * 256 + d;
        float cm = pm[o];
        float nm = fmaxf(m, cm);
        float e0 = __expf(m - nm);
        float e1 = __expf(cm - nm);
        Z = Z * e0 + pz[o] * e1;
        acc = acc * e0 + pa[o] * e1;
        m = nm;
    }
    xcat[b * 1024 + head * 256 + d] = acc / Z;
}

__global__ void mlp_k(const float* __restrict__ X, const float* __restrict__ Wm,
                      const float* __restrict__ bias, float* __restrict__ Y,
                      int Kdim, int do_relu)
{
    __shared__ float sx[1024];
    int b = blockIdx.x, c = threadIdx.x;
    for (int t = c; t < Kdim; t += 256) sx[t] = X[b * Kdim + t];
    __syncthreads();
    float s = 0.f;
#pragma unroll 4
    for (int t = 0; t < Kdim; t++) s = fmaf(sx[t], Wm[c * Kdim + t], s);
    s += bias[c];
    if (do_relu) s = fmaxf(s, 0.f);
    Y[b * 256 + c] = s;
}

// ---------------------------------------------------------------------------
extern "C" void kernel_launch(void* const* d_in, const int* in_sizes, int n_in,
                              void* d_out, int out_size)
{
    float* pool = nullptr;
    cudaGetSymbolAddress((void**)&pool, g_pool);

    cudaFuncSetAttribute(gemm_mma, cudaFuncAttributeMaxDynamicSharedMemorySize, GEMM_SMEM);

    const float* q   = (const float*)d_in[0];
    const float* k   = (const float*)d_in[1];
    const float* v   = (const float*)d_in[2];
    const float* wq  = (const float*)d_in[3];
    const float* bq  = (const float*)d_in[4];
    const float* wk  = (const float*)d_in[5];
    const float* bk  = (const float*)d_in[6];
    const float* wv  = (const float*)d_in[7];
    const float* bv  = (const float*)d_in[8];
    const float* g1  = (const float*)d_in[9];
    const float* be1 = (const float*)d_in[10];
    const float* wl1 = (const float*)d_in[11];
    const float* bl1 = (const float*)d_in[12];
    const float* g2  = (const float*)d_in[13];
    const float* be2 = (const float*)d_in[14];
    const float* wl2 = (const float*)d_in[15];
    const float* bl2 = (const float*)d_in[16];
    const float* mw0 = (const float*)d_in[17];
    const float* mb0 = (const float*)d_in[18];
    const float* mw1 = (const float*)d_in[19];
    const float* mb1 = (const float*)d_in[20];
    const float* mw2 = (const float*)d_in[21];
    const float* mb2 = (const float*)d_in[22];

    float* Qb[2] = {pool + 0 * MD_, pool + 1 * MD_};
    float* Kb[2] = {pool + 2 * MD_, pool + 3 * MD_};
    float* Vb[2] = {pool + 4 * MD_, pool + 5 * MD_};
    float* W     = pool + 6 * MD_;
    float* W2    = pool + 7 * MD_;
    float* ssum  = pool + O_SSUM;
    float* ssq   = pool + O_SSQ;
    float* scale = pool + O_SCALE;
    float* shift = pool + O_SHIFT;
    float* pm    = pool + O_PM;
    float* pz    = pool + O_PZ;
    float* pa    = pool + O_PA;
    float* xcat  = pool + O_XCAT;
    float* h0    = pool + O_H0;
    float* h1    = pool + O_H1;
    __nv_bfloat16* whi = (__nv_bfloat16*)(pool + O_WHI);
    __nv_bfloat16* wlo = (__nv_bfloat16*)(pool + O_WLO);

    // split all 20 weight matrices to bf16 hi/lo  (arr order: wq,wk,wv,wl1,wl2)
    wsplit<<<5120, 256>>>(wq, wk, wv, wl1, wl2, whi, wlo);

    for (int i = 0; i < 4; i++) {
        const float* Qs = i ? Qb[(i - 1) & 1] : q;
        const float* Ks = i ? Kb[(i - 1) & 1] : k;
        const float* Vs = i ? Vb[(i - 1) & 1] : v;
        float* Qd = Qb[i & 1];
        float* Kd = Kb[i & 1];
        float* Vd = Vb[i & 1];

        const __nv_bfloat16* whq  = whi + (0 * 4 + i) * 65536;
        const __nv_bfloat16* wlq  = wlo + (0 * 4 + i) * 65536;
        const __nv_bfloat16* whk  = whi + (1 * 4 + i) * 65536;
        const __nv_bfloat16* wlk  = wlo + (1 * 4 + i) * 65536;
        const __nv_bfloat16* whv  = whi + (2 * 4 + i) * 65536;
        const __nv_bfloat16* wlv  = wlo + (2 * 4 + i) * 65536;
        const __nv_bfloat16* wh1  = whi + (3 * 4 + i) * 65536;
        const __nv_bfloat16* wl1s = wlo + (3 * 4 + i) * 65536;
        const __nv_bfloat16* wh2  = whi + (4 * 4 + i) * 65536;
        const __nv_bfloat16* wl2s = wlo + (4 * 4 + i) * 65536;

        gemm_mma<<<512, 512, GEMM_SMEM>>>(Qs, whq, wlq, bq + i * 256,
                                          nullptr, nullptr, Qd, nullptr, nullptr);
        gemm_mma<<<512, 512, GEMM_SMEM>>>(Ks, whk, wlk, bk + i * 256,
                                          nullptr, nullptr, Kd, nullptr, nullptr);
        gemm_mma<<<512, 512, GEMM_SMEM>>>(Vs, whv, wlv, bv + i * 256,
                                          nullptr, nullptr, Vd, nullptr, nullptr);

        zerok<<<1, 256>>>(ssum, ssq);
        subk_stats<<<512, 256>>>(Kd, Qd, W, ssum, ssq);
        bnfinal<<<1, 256>>>(ssum, ssq, g1 + i * 256, be1 + i * 256, scale, shift);

        zerok<<<1, 256>>>(ssum, ssq);
        gemm_mma<<<512, 512, GEMM_SMEM>>>(W, wh1, wl1s, bl1 + i * 256,
                                          scale, shift, W2, ssum, ssq);
        bnfinal<<<1, 256>>>(ssum, ssq, g2 + i * 256, be2 + i * 256, scale, shift);

        gemm_mma<<<512, 512, GEMM_SMEM>>>(W2, wh2, wl2s, bl2 + i * 256,
                                          scale, shift, W, nullptr, nullptr);

        smax_part<<<dim3(32, 16), 256>>>(W, Vd, pm, pz, pa);
        smax_comb<<<32, 256>>>(pm, pz, pa, xcat, i);
    }

    mlp_k<<<32, 256>>>(xcat, mw0, mb0, h0, 1024, 1);
    mlp_k<<<32, 256>>>(h0, mw1, mb1, h1, 256, 1);
    mlp_k<<<32, 256>>>(h1, mw2, mb2, (float*)d_out, 256, 0);
}

// round 9
// speedup vs baseline: 2.1954x; 1.0903x over previous
#include <cuda_runtime.h>
#include <cuda_bf16.h>
#include <cstdint>

// Problem constants: S=2048, B=32, D=256, H=4.  M = S*B = 65536 rows.
#define MROWS 65536
static constexpr size_t MD_ = 16777216ull;   // 65536*256

__device__ float g_pool[8ull * 16777216ull + 4194304ull];

static constexpr size_t O_SMALL = 8ull * 16777216ull;
static constexpr size_t O_SSUM  = O_SMALL;
static constexpr size_t O_SSQ   = O_SMALL + 256;
static constexpr size_t O_SCALE = O_SMALL + 512;
static constexpr size_t O_SHIFT = O_SMALL + 768;
static constexpr size_t O_PM    = O_SMALL + 1024;
static constexpr size_t O_PZ    = O_PM + 16 * 32 * 256;
static constexpr size_t O_PA    = O_PZ + 16 * 32 * 256;
static constexpr size_t O_XCAT  = O_PA + 16 * 32 * 256;
static constexpr size_t O_H0    = O_XCAT + 32 * 1024;
static constexpr size_t O_H1    = O_H0 + 32 * 256;
static constexpr size_t O_WHI   = O_SMALL + 1048576;
static constexpr size_t O_WLO   = O_WHI + 655360;

// ---------------------------------------------------------------------------
__device__ __forceinline__ uint32_t s2u(const void* p) {
    uint32_t a;
    asm("{ .reg .u64 t; cvta.to.shared.u64 t, %1; cvt.u32.u64 %0, t; }" : "=r"(a) : "l"(p));
    return a;
}
__device__ __forceinline__ void mma16816(float* d, const uint32_t* a, const uint32_t* b) {
    asm volatile(
        "mma.sync.aligned.m16n8k16.row.col.f32.bf16.bf16.f32 "
        "{%0,%1,%2,%3}, {%4,%5,%6,%7}, {%8,%9}, {%0,%1,%2,%3};"
        : "+f"(d[0]), "+f"(d[1]), "+f"(d[2]), "+f"(d[3])
        : "r"(a[0]), "r"(a[1]), "r"(a[2]), "r"(a[3]), "r"(b[0]), "r"(b[1]));
}
__device__ __forceinline__ void ldsm4(uint32_t* r, uint32_t a) {
    asm volatile("ldmatrix.sync.aligned.m8n8.x4.shared.b16 {%0,%1,%2,%3}, [%4];"
        : "=r"(r[0]), "=r"(r[1]), "=r"(r[2]), "=r"(r[3]) : "r"(a));
}
__device__ __forceinline__ void cpasync16(uint32_t dst, const void* src) {
    asm volatile("cp.async.cg.shared.global [%0], [%1], 16;" :: "r"(dst), "l"(src));
}
__device__ __forceinline__ void cpcommit() { asm volatile("cp.async.commit_group;"); }
__device__ __forceinline__ void cpwait0()  { asm volatile("cp.async.wait_group 0;" ::: "memory"); }
#define STS128(a, v)                                                            \
    asm volatile("st.shared.v4.b32 [%0], {%1,%2,%3,%4};"                        \
        :: "r"(a), "r"((v).x), "r"((v).y), "r"((v).z), "r"((v).w) : "memory")

// SMEM layout (bytes):
//   0    : ssum[256] floats, ssq[256] floats
//   2048 : stage0 { A_hi 4KB | A_lo 4KB | W_hi 16KB | W_lo 16KB } = 40KB, stage1 next
#define STG_ALO   4096u
#define STG_WHI   8192u
#define STG_WLO   24576u
#define STG_SIZE  40960u
#define GEMM_SMEM (2048 + 2 * 40960)   // 83968 bytes -> 2 CTAs/SM

// ---------------------------------------------------------------------------
// Core HMMA GEMM: tile M=64 x N=256, 256 threads (8 warps, 2x4), warp 32x64.
// C = act(A) @ W^T + bias ; act = relu(a*ascale+ashift) if BN.
// Error-compensated: D += Ahi*Whi + Alo*Whi + Ahi*Wlo (fp32 accum).
// SUB: w = C - Qsub, write Wout, stats on w.  STATS: column sum/sumsq atomics.
// ---------------------------------------------------------------------------
template<bool BN, bool SUB, bool STATS>
__device__ __forceinline__ void gemm_core(
    const float* __restrict__ A,
    const __nv_bfloat16* __restrict__ Wh,
    const __nv_bfloat16* __restrict__ Wl,
    const float* __restrict__ bias,
    const float* __restrict__ ascale,
    const float* __restrict__ ashift,
    float* __restrict__ C,
    const float* __restrict__ Qsub,
    float* __restrict__ Wout,
    float* __restrict__ gsum, float* __restrict__ gsq)
{
    extern __shared__ __align__(16) char smem[];
    const uint32_t sb = s2u(smem);
    const int t = threadIdx.x, w = t >> 5, l = t & 31;
    const int wr = w >> 2, wc = w & 3;           // 2x4 warp grid; warp tile 32x64
    const size_t r0 = (size_t)blockIdx.x * 64;

    if (STATS) {
        ((float*)smem)[t] = 0.f;
        ((float*)smem)[t + 256] = 0.f;
    }

    const uint32_t stg0 = sb + 2048;

    // loader mapping
    const int arow = t >> 2, ag = t & 3;         // A: 64 rows x 4 granules
    const uint32_t a_sts = (uint32_t)(arow * 64 + ((ag ^ ((arow >> 1) & 3)) << 4));
    const int wrow = t >> 2, wg = t & 3;         // W: rows wrow + 64j
    const uint32_t w_sw = (uint32_t)((wg ^ ((wrow >> 1) & 3)) << 4);
    const uint32_t w_sts = (uint32_t)(wrow * 64) + w_sw;

    // ldmatrix lane constants
    const int a_base_row = wr * 32 + (l & 15);
    const int sa = (a_base_row >> 1) & 3;
    const uint32_t a_off0 = (uint32_t)(a_base_row * 64);
    const int b_base_row = wc * 64 + ((l >> 4) << 3) + (l & 7);
    const int sbz = (b_base_row >> 1) & 3;
    const uint32_t b_off0 = (uint32_t)(b_base_row * 64);
    const int a_gl = l >> 4;
    const int b_gl = (l >> 3) & 1;

    float acc[2][8][4];
#pragma unroll
    for (int mt = 0; mt < 2; mt++)
#pragma unroll
        for (int nt = 0; nt < 8; nt++)
#pragma unroll
            for (int j = 0; j < 4; j++) acc[mt][nt][j] = 0.f;

    float af[8];

    // ===== prologue: chunk 0 =====
    {
        const float4* p = (const float4*)(A + (r0 + arow) * 256 + ag * 8);
        float4 v0 = p[0], v1 = p[1];
        af[0] = v0.x; af[1] = v0.y; af[2] = v0.z; af[3] = v0.w;
        af[4] = v1.x; af[5] = v1.y; af[6] = v1.z; af[7] = v1.w;
        if (BN) {
            int kk = ag * 8;
#pragma unroll
            for (int i = 0; i < 8; i++)
                af[i] = fmaxf(fmaf(af[i], ascale[kk + i], ashift[kk + i]), 0.f);
        }
        size_t ws = (size_t)wrow * 256 + wg * 8;
#pragma unroll
        for (int j = 0; j < 4; j++) {
            cpasync16(stg0 + STG_WHI + w_sts + j * 4096u, Wh + ws + (size_t)j * 64 * 256);
            cpasync16(stg0 + STG_WLO + w_sts + j * 4096u, Wl + ws + (size_t)j * 64 * 256);
        }
        cpcommit();
        uint4 hv, lv;
        __nv_bfloat162* hp = (__nv_bfloat162*)&hv;
        __nv_bfloat162* lp = (__nv_bfloat162*)&lv;
#pragma unroll
        for (int i = 0; i < 4; i++) {
            __nv_bfloat16 h0 = __float2bfloat16(af[2 * i]);
            __nv_bfloat16 h1 = __float2bfloat16(af[2 * i + 1]);
            hp[i].x = h0; hp[i].y = h1;
            lp[i].x = __float2bfloat16(af[2 * i]     - __bfloat162float(h0));
            lp[i].y = __float2bfloat16(af[2 * i + 1] - __bfloat162float(h1));
        }
        STS128(stg0 + a_sts, hv);
        STS128(stg0 + STG_ALO + a_sts, lv);
        cpwait0();
    }
    __syncthreads();

    // ===== mainloop: 8 chunks of k32 =====
    for (int c = 0; c < 8; c++) {
        const uint32_t stgs = stg0 + (uint32_t)(c & 1) * STG_SIZE;
        const uint32_t stgn = stg0 + (uint32_t)((c + 1) & 1) * STG_SIZE;

        if (c < 7) {
            const float4* p = (const float4*)(A + (r0 + arow) * 256 + (c + 1) * 32 + ag * 8);
            float4 v0 = p[0], v1 = p[1];
            af[0] = v0.x; af[1] = v0.y; af[2] = v0.z; af[3] = v0.w;
            af[4] = v1.x; af[5] = v1.y; af[6] = v1.z; af[7] = v1.w;
            if (BN) {
                int kk = (c + 1) * 32 + ag * 8;
#pragma unroll
                for (int i = 0; i < 8; i++)
                    af[i] = fmaxf(fmaf(af[i], ascale[kk + i], ashift[kk + i]), 0.f);
            }
            size_t ws = (size_t)wrow * 256 + (c + 1) * 32 + wg * 8;
#pragma unroll
            for (int j = 0; j < 4; j++) {
                cpasync16(stgn + STG_WHI + w_sts + j * 4096u, Wh + ws + (size_t)j * 64 * 256);
                cpasync16(stgn + STG_WLO + w_sts + j * 4096u, Wl + ws + (size_t)j * 64 * 256);
            }
            cpcommit();
        }

        // ---- compute chunk c ----
#pragma unroll
        for (int ks = 0; ks < 2; ks++) {
            uint32_t ah[2][4], al[2][4], bb[4];
            const uint32_t agoff = (uint32_t)(((ks * 2 + a_gl) ^ sa) << 4);
            ldsm4(ah[0], stgs + a_off0 + agoff);
            ldsm4(ah[1], stgs + a_off0 + 1024 + agoff);
            ldsm4(al[0], stgs + STG_ALO + a_off0 + agoff);
            ldsm4(al[1], stgs + STG_ALO + a_off0 + 1024 + agoff);
            const uint32_t bgoff = (uint32_t)(((ks * 2 + b_gl) ^ sbz) << 4);
#pragma unroll
            for (int n2 = 0; n2 < 4; n2++) {
                const uint32_t brow = b_off0 + (uint32_t)(n2 * 1024);
                ldsm4(bb, stgs + STG_WHI + brow + bgoff);
                mma16816(acc[0][n2 * 2],     ah[0], bb);
                mma16816(acc[0][n2 * 2 + 1], ah[0], bb + 2);
                mma16816(acc[1][n2 * 2],     ah[1], bb);
                mma16816(acc[1][n2 * 2 + 1], ah[1], bb + 2);
                mma16816(acc[0][n2 * 2],     al[0], bb);
                mma16816(acc[0][n2 * 2 + 1], al[0], bb + 2);
                mma16816(acc[1][n2 * 2],     al[1], bb);
                mma16816(acc[1][n2 * 2 + 1], al[1], bb + 2);
                ldsm4(bb, stgs + STG_WLO + brow + bgoff);
                mma16816(acc[0][n2 * 2],     ah[0], bb);
                mma16816(acc[0][n2 * 2 + 1], ah[0], bb + 2);
                mma16816(acc[1][n2 * 2],     ah[1], bb);
                mma16816(acc[1][n2 * 2 + 1], ah[1], bb + 2);
            }
        }

        if (c < 7) {
            uint4 hv, lv;
            __nv_bfloat162* hp = (__nv_bfloat162*)&hv;
            __nv_bfloat162* lp = (__nv_bfloat162*)&lv;
#pragma unroll
            for (int i = 0; i < 4; i++) {
                __nv_bfloat16 h0 = __float2bfloat16(af[2 * i]);
                __nv_bfloat16 h1 = __float2bfloat16(af[2 * i + 1]);
                hp[i].x = h0; hp[i].y = h1;
                lp[i].x = __float2bfloat16(af[2 * i]     - __bfloat162float(h0));
                lp[i].y = __float2bfloat16(af[2 * i + 1] - __bfloat162float(h1));
            }
            STS128(stgn + a_sts, hv);
            STS128(stgn + STG_ALO + a_sts, lv);
            cpwait0();
            __syncthreads();
        }
    }

    // ===== epilogue =====
    const int erow = wr * 32 + (l >> 2);
#pragma unroll
    for (int nt = 0; nt < 8; nt++) {
        const int col = wc * 64 + nt * 8 + (l & 3) * 2;
        const float2 bb2 = *(const float2*)(bias + col);
        float s0 = 0.f, s1 = 0.f, q0 = 0.f, q1 = 0.f;
#pragma unroll
        for (int mt = 0; mt < 2; mt++) {
            const size_t row = r0 + erow + mt * 16;
            float v0 = acc[mt][nt][0] + bb2.x;
            float v1 = acc[mt][nt][1] + bb2.y;
            float v2 = acc[mt][nt][2] + bb2.x;
            float v3 = acc[mt][nt][3] + bb2.y;
            *(float2*)(C + row * 256 + col)       = make_float2(v0, v1);
            *(float2*)(C + (row + 8) * 256 + col) = make_float2(v2, v3);
            if (SUB) {
                float2 qa = *(const float2*)(Qsub + row * 256 + col);
                float2 qb = *(const float2*)(Qsub + (row + 8) * 256 + col);
                float w0 = v0 - qa.x, w1 = v1 - qa.y;
                float w2 = v2 - qb.x, w3 = v3 - qb.y;
                *(float2*)(Wout + row * 256 + col)       = make_float2(w0, w1);
                *(float2*)(Wout + (row + 8) * 256 + col) = make_float2(w2, w3);
                s0 += w0 + w2; s1 += w1 + w3;
                q0 += w0 * w0 + w2 * w2; q1 += w1 * w1 + w3 * w3;
            } else if (STATS) {
                s0 += v0 + v2; s1 += v1 + v3;
                q0 += v0 * v0 + v2 * v2; q1 += v1 * v1 + v3 * v3;
            }
        }
        if (STATS) {
            float* ss = (float*)smem;
            atomicAdd(ss + col,           s0);
            atomicAdd(ss + col + 1,       s1);
            atomicAdd(ss + 256 + col,     q0);
            atomicAdd(ss + 256 + col + 1, q1);
        }
    }

    if (STATS) {
        __syncthreads();
        atomicAdd(gsum + t, ((float*)smem)[t]);
        atomicAdd(gsq  + t, ((float*)smem)[256 + t]);
    }
}

// ---- wrappers ----
__global__ __launch_bounds__(256, 2)
void gemm_plain(const float* A, const __nv_bfloat16* Wh, const __nv_bfloat16* Wl,
                const float* bias, float* C)
{
    gemm_core<false, false, false>(A, Wh, Wl, bias, nullptr, nullptr, C,
                                   nullptr, nullptr, nullptr, nullptr);
}
__global__ __launch_bounds__(256, 2)
void gemm_kv(const float* Ka, const __nv_bfloat16* KWh, const __nv_bfloat16* KWl,
             const float* kb, float* Kd,
             const float* Va, const __nv_bfloat16* VWh, const __nv_bfloat16* VWl,
             const float* vb, float* Vd,
             const float* Qd, float* Wout, float* gsum, float* gsq)
{
    if (blockIdx.y == 0)
        gemm_core<false, true, true>(Ka, KWh, KWl, kb, nullptr, nullptr, Kd,
                                     Qd, Wout, gsum, gsq);
    else
        gemm_core<false, false, false>(Va, VWh, VWl, vb, nullptr, nullptr, Vd,
                                       nullptr, nullptr, nullptr, nullptr);
}
__global__ __launch_bounds__(256, 2)
void gemm_bn_stats(const float* A, const __nv_bfloat16* Wh, const __nv_bfloat16* Wl,
                   const float* bias, const float* ascale, const float* ashift,
                   float* C, float* gsum, float* gsq)
{
    gemm_core<true, false, true>(A, Wh, Wl, bias, ascale, ashift, C,
                                 nullptr, nullptr, gsum, gsq);
}
__global__ __launch_bounds__(256, 2)
void gemm_bn(const float* A, const __nv_bfloat16* Wh, const __nv_bfloat16* Wl,
             const float* bias, const float* ascale, const float* ashift, float* C)
{
    gemm_core<true, false, false>(A, Wh, Wl, bias, ascale, ashift, C,
                                  nullptr, nullptr, nullptr, nullptr);
}

// ---------------------------------------------------------------------------
__global__ void wsplit(const float* __restrict__ w0, const float* __restrict__ w1,
                       const float* __restrict__ w2, const float* __restrict__ w3,
                       const float* __restrict__ w4,
                       __nv_bfloat16* __restrict__ hi, __nv_bfloat16* __restrict__ lo)
{
    size_t i = (size_t)blockIdx.x * 256 + threadIdx.x;
    size_t a = i >> 18, r = i & 262143;
    const float* s = (a == 0) ? w0 : (a == 1) ? w1 : (a == 2) ? w2 : (a == 3) ? w3 : w4;
    float x = s[r];
    __nv_bfloat16 h = __float2bfloat16(x);
    hi[i] = h;
    lo[i] = __float2bfloat16(x - __bfloat162float(h));
}

__global__ void zerok(float* a, float* b)
{
    a[threadIdx.x] = 0.f;
    b[threadIdx.x] = 0.f;
}

__global__ void bnfinal(const float* __restrict__ s, const float* __restrict__ sq,
                        const float* __restrict__ gamma, const float* __restrict__ beta,
                        float* __restrict__ scale, float* __restrict__ shift)
{
    int c = threadIdx.x;
    const float inv = 1.f / 65536.f;
    float m = s[c] * inv;
    float v = sq[c] * inv - m * m;
    float r = rsqrtf(v + 1e-5f);
    float sc = r * gamma[c];
    scale[c] = sc;
    shift[c] = beta[c] - m * sc;
}

// Online softmax over S fused with weighted V-sum (16-way split over S)
__global__ void smax_part(const float* __restrict__ W3, const float* __restrict__ V,
                          float* __restrict__ pm, float* __restrict__ pz,
                          float* __restrict__ pa)
{
    int b = blockIdx.x, ch = blockIdx.y, d = threadIdx.x;
    float m = -1e30f, Z = 0.f, acc = 0.f;
#pragma unroll 4
    for (int j = 0; j < 128; j++) {
        int s_ = ch * 128 + j;
        size_t idx = ((size_t)(s_ * 32 + b)) * 256 + d;
        float w = W3[idx];
        float v = V[idx];
        float nm = fmaxf(m, w);
        float e0 = __expf(m - nm);
        float e1 = __expf(w - nm);
        Z = Z * e0 + e1;
        acc = fmaf(v, e1, acc * e0);
        m = nm;
    }
    int o = (ch * 32 + b) * 256 + d;
    pm[o] = m; pz[o] = Z; pa[o] = acc;
}

__global__ void smax_comb(const float* __restrict__ pm, const float* __restrict__ pz,
                          const float* __restrict__ pa, float* __restrict__ xcat,
                          int head)
{
    int b = blockIdx.x, d = threadIdx.x;
    float m = -1e30f, Z = 0.f, acc = 0.f;
#pragma unroll
    for (int ch = 0; ch < 16; ch++) {
        int o = (ch * 32 + b) * 256 + d;
        float cm = pm[o];
        float nm = fmaxf(m, cm);
        float e0 = __expf(m - nm);
        float e1 = __expf(cm - nm);
        Z = Z * e0 + pz[o] * e1;
        acc = acc * e0 + pa[o] * e1;
        m = nm;
    }
    xcat[b * 1024 + head * 256 + d] = acc / Z;
}

__global__ void mlp_k(const float* __restrict__ X, const float* __restrict__ Wm,
                      const float* __restrict__ bias, float* __restrict__ Y,
                      int Kdim, int do_relu)
{
    __shared__ float sx[1024];
    int b = blockIdx.x, c = threadIdx.x;
    for (int t = c; t < Kdim; t += 256) sx[t] = X[b * Kdim + t];
    __syncthreads();
    float s = 0.f;
#pragma unroll 4
    for (int t = 0; t < Kdim; t++) s = fmaf(sx[t], Wm[c * Kdim + t], s);
    s += bias[c];
    if (do_relu) s = fmaxf(s, 0.f);
    Y[b * 256 + c] = s;
}

// ---------------------------------------------------------------------------
extern "C" void kernel_launch(void* const* d_in, const int* in_sizes, int n_in,
                              void* d_out, int out_size)
{
    float* pool = nullptr;
    cudaGetSymbolAddress((void**)&pool, g_pool);

    cudaFuncSetAttribute(gemm_plain,    cudaFuncAttributeMaxDynamicSharedMemorySize, GEMM_SMEM);
    cudaFuncSetAttribute(gemm_kv,       cudaFuncAttributeMaxDynamicSharedMemorySize, GEMM_SMEM);
    cudaFuncSetAttribute(gemm_bn_stats, cudaFuncAttributeMaxDynamicSharedMemorySize, GEMM_SMEM);
    cudaFuncSetAttribute(gemm_bn,       cudaFuncAttributeMaxDynamicSharedMemorySize, GEMM_SMEM);

    const float* q   = (const float*)d_in[0];
    const float* k   = (const float*)d_in[1];
    const float* v   = (const float*)d_in[2];
    const float* wq  = (const float*)d_in[3];
    const float* bq  = (const float*)d_in[4];
    const float* wk  = (const float*)d_in[5];
    const float* bk  = (const float*)d_in[6];
    const float* wv  = (const float*)d_in[7];
    const float* bv  = (const float*)d_in[8];
    const float* g1  = (const float*)d_in[9];
    const float* be1 = (const float*)d_in[10];
    const float* wl1 = (const float*)d_in[11];
    const float* bl1 = (const float*)d_in[12];
    const float* g2  = (const float*)d_in[13];
    const float* be2 = (const float*)d_in[14];
    const float* wl2 = (const float*)d_in[15];
    const float* bl2 = (const float*)d_in[16];
    const float* mw0 = (const float*)d_in[17];
    const float* mb0 = (const float*)d_in[18];
    const float* mw1 = (const float*)d_in[19];
    const float* mb1 = (const float*)d_in[20];
    const float* mw2 = (const float*)d_in[21];
    const float* mb2 = (const float*)d_in[22];

    float* Qb[2] = {pool + 0 * MD_, pool + 1 * MD_};
    float* Kb[2] = {pool + 2 * MD_, pool + 3 * MD_};
    float* Vb[2] = {pool + 4 * MD_, pool + 5 * MD_};
    float* W     = pool + 6 * MD_;
    float* W2    = pool + 7 * MD_;
    float* ssum  = pool + O_SSUM;
    float* ssq   = pool + O_SSQ;
    float* scale = pool + O_SCALE;
    float* shift = pool + O_SHIFT;
    float* pm    = pool + O_PM;
    float* pz    = pool + O_PZ;
    float* pa    = pool + O_PA;
    float* xcat  = pool + O_XCAT;
    float* h0    = pool + O_H0;
    float* h1    = pool + O_H1;
    __nv_bfloat16* whi = (__nv_bfloat16*)(pool + O_WHI);
    __nv_bfloat16* wlo = (__nv_bfloat16*)(pool + O_WLO);

    wsplit<<<5120, 256>>>(wq, wk, wv, wl1, wl2, whi, wlo);

    const int NT = MROWS / 64;   // 1024 row tiles

    for (int i = 0; i < 4; i++) {
        const float* Qs = i ? Qb[(i - 1) & 1] : q;
        const float* Ks = i ? Kb[(i - 1) & 1] : k;
        const float* Vs = i ? Vb[(i - 1) & 1] : v;
        float* Qd = Qb[i & 1];
        float* Kd = Kb[i & 1];
        float* Vd = Vb[i & 1];

        const __nv_bfloat16* whq  = whi + (0 * 4 + i) * 65536;
        const __nv_bfloat16* wlq  = wlo + (0 * 4 + i) * 65536;
        const __nv_bfloat16* whk  = whi + (1 * 4 + i) * 65536;
        const __nv_bfloat16* wlk  = wlo + (1 * 4 + i) * 65536;
        const __nv_bfloat16* whv  = whi + (2 * 4 + i) * 65536;
        const __nv_bfloat16* wlv  = wlo + (2 * 4 + i) * 65536;
        const __nv_bfloat16* wh1  = whi + (3 * 4 + i) * 65536;
        const __nv_bfloat16* wl1s = wlo + (3 * 4 + i) * 65536;
        const __nv_bfloat16* wh2  = whi + (4 * 4 + i) * 65536;
        const __nv_bfloat16* wl2s = wlo + (4 * 4 + i) * 65536;

        gemm_plain<<<NT, 256, GEMM_SMEM>>>(Qs, whq, wlq, bq + i * 256, Qd);

        zerok<<<1, 256>>>(ssum, ssq);
        gemm_kv<<<dim3(NT, 2), 256, GEMM_SMEM>>>(
            Ks, whk, wlk, bk + i * 256, Kd,
            Vs, whv, wlv, bv + i * 256, Vd,
            Qd, W, ssum, ssq);
        bnfinal<<<1, 256>>>(ssum, ssq, g1 + i * 256, be1 + i * 256, scale, shift);

        zerok<<<1, 256>>>(ssum, ssq);
        gemm_bn_stats<<<NT, 256, GEMM_SMEM>>>(W, wh1, wl1s, bl1 + i * 256,
                                              scale, shift, W2, ssum, ssq);
        bnfinal<<<1, 256>>>(ssum, ssq, g2 + i * 256, be2 + i * 256, scale, shift);

        gemm_bn<<<NT, 256, GEMM_SMEM>>>(W2, wh2, wl2s, bl2 + i * 256, scale, shift, W);

        smax_part<<<dim3(32, 16), 256>>>(W, Vd, pm, pz, pa);
        smax_comb<<<32, 256>>>(pm, pz, pa, xcat, i);
    }

    mlp_k<<<32, 256>>>(xcat, mw0, mb0, h0, 1024, 1);
    mlp_k<<<32, 256>>>(h0, mw1, mb1, h1, 256, 1);
    mlp_k<<<32, 256>>>(h1, mw2, mb2, (float*)d_out, 256, 0);
}

// round 10
// speedup vs baseline: 2.6410x; 1.2030x over previous
#include <cuda_runtime.h>
#include <cuda_fp16.h>
#include <cstdint>

// Problem constants: S=2048, B=32, D=256, H=4.  M = S*B = 65536 rows.
#define MROWS 65536
static constexpr size_t MD_ = 16777216ull;   // 65536*256

__device__ float g_pool[8ull * 16777216ull + 4194304ull];

static constexpr size_t O_SMALL = 8ull * 16777216ull;
static constexpr size_t O_SSUM  = O_SMALL;
static constexpr size_t O_SSQ   = O_SMALL + 256;
static constexpr size_t O_SCALE = O_SMALL + 512;
static constexpr size_t O_SHIFT = O_SMALL + 768;
static constexpr size_t O_PM    = O_SMALL + 1024;
static constexpr size_t O_PZ    = O_PM + 16 * 32 * 256;
static constexpr size_t O_PA    = O_PZ + 16 * 32 * 256;
static constexpr size_t O_XCAT  = O_PA + 16 * 32 * 256;
static constexpr size_t O_H0    = O_XCAT + 32 * 1024;
static constexpr size_t O_H1    = O_H0 + 32 * 256;
static constexpr size_t O_WF16  = O_SMALL + 1048576;   // fp16 weights (20 * 65536)

// ---------------------------------------------------------------------------
__device__ __forceinline__ uint32_t s2u(const void* p) {
    uint32_t a;
    asm("{ .reg .u64 t; cvta.to.shared.u64 t, %1; cvt.u32.u64 %0, t; }" : "=r"(a) : "l"(p));
    return a;
}
__device__ __forceinline__ void mma16816(float* d, const uint32_t* a, const uint32_t* b) {
    asm volatile(
        "mma.sync.aligned.m16n8k16.row.col.f32.f16.f16.f32 "
        "{%0,%1,%2,%3}, {%4,%5,%6,%7}, {%8,%9}, {%0,%1,%2,%3};"
        : "+f"(d[0]), "+f"(d[1]), "+f"(d[2]), "+f"(d[3])
        : "r"(a[0]), "r"(a[1]), "r"(a[2]), "r"(a[3]), "r"(b[0]), "r"(b[1]));
}
__device__ __forceinline__ void ldsm4(uint32_t* r, uint32_t a) {
    asm volatile("ldmatrix.sync.aligned.m8n8.x4.shared.b16 {%0,%1,%2,%3}, [%4];"
        : "=r"(r[0]), "=r"(r[1]), "=r"(r[2]), "=r"(r[3]) : "r"(a));
}
__device__ __forceinline__ void cpasync16(uint32_t dst, const void* src) {
    asm volatile("cp.async.cg.shared.global [%0], [%1], 16;" :: "r"(dst), "l"(src));
}
__device__ __forceinline__ void cpcommit() { asm volatile("cp.async.commit_group;"); }
__device__ __forceinline__ void cpwait0()  { asm volatile("cp.async.wait_group 0;" ::: "memory"); }
#define STS128(a, v)                                                            \
    asm volatile("st.shared.v4.b32 [%0], {%1,%2,%3,%4};"                        \
        :: "r"(a), "r"((v).x), "r"((v).y), "r"((v).z), "r"((v).w) : "memory")

// SMEM layout (bytes):
//   0    : ssum[256] floats, ssq[256] floats
//   2048 : stage0 { A_hi 4KB | A_lo 4KB | W 16KB } = 24KB, stage1 next
#define STG_ALO   4096u
#define STG_W     8192u
#define STG_SIZE  24576u
#define GEMM_SMEM (2048 + 2 * 24576)   // 51200 bytes -> 2 CTAs/SM (reg-limited)

// ---------------------------------------------------------------------------
// Core HMMA GEMM: tile M=64 x N=256, 256 threads (8 warps, 2x4), warp 32x64.
// C = act(A) @ W^T + bias ; act = relu(a*ascale+ashift) if BN.
// fp16 2-term: D += Ahi*W + Alo*W  (A split to fp16 hi+lo, W single fp16,
// fp32 accumulate; only W's fp16 quantization error remains, ~2^-12).
// SUB: w = C - Qsub, write Wout, stats on w.  STATS: column sum/sumsq atomics.
// ---------------------------------------------------------------------------
template<bool BN, bool SUB, bool STATS>
__device__ __forceinline__ void gemm_core(
    const float* __restrict__ A,
    const __half* __restrict__ Wh,
    const float* __restrict__ bias,
    const float* __restrict__ ascale,
    const float* __restrict__ ashift,
    float* __restrict__ C,
    const float* __restrict__ Qsub,
    float* __restrict__ Wout,
    float* __restrict__ gsum, float* __restrict__ gsq)
{
    extern __shared__ __align__(16) char smem[];
    const uint32_t sb = s2u(smem);
    const int t = threadIdx.x, w = t >> 5, l = t & 31;
    const int wr = w >> 2, wc = w & 3;           // 2x4 warp grid; warp tile 32x64
    const size_t r0 = (size_t)blockIdx.x * 64;

    if (STATS) {
        ((float*)smem)[t] = 0.f;
        ((float*)smem)[t + 256] = 0.f;
    }

    const uint32_t stg0 = sb + 2048;

    // loader mapping
    const int arow = t >> 2, ag = t & 3;         // A: 64 rows x 4 granules
    const uint32_t a_sts = (uint32_t)(arow * 64 + ((ag ^ ((arow >> 1) & 3)) << 4));
    const int wrow = t >> 2, wg = t & 3;         // W: rows wrow + 64j
    const uint32_t w_sts = (uint32_t)(wrow * 64) + (uint32_t)((wg ^ ((wrow >> 1) & 3)) << 4);

    // ldmatrix lane constants
    const int a_base_row = wr * 32 + (l & 15);
    const int sa = (a_base_row >> 1) & 3;
    const uint32_t a_off0 = (uint32_t)(a_base_row * 64);
    const int b_base_row = wc * 64 + ((l >> 4) << 3) + (l & 7);
    const int sbz = (b_base_row >> 1) & 3;
    const uint32_t b_off0 = (uint32_t)(b_base_row * 64);
    const int a_gl = l >> 4;
    const int b_gl = (l >> 3) & 1;

    float acc[2][8][4];
#pragma unroll
    for (int mt = 0; mt < 2; mt++)
#pragma unroll
        for (int nt = 0; nt < 8; nt++)
#pragma unroll
            for (int j = 0; j < 4; j++) acc[mt][nt][j] = 0.f;

    float af[8];

    // ===== prologue: chunk 0 =====
    {
        const float4* p = (const float4*)(A + (r0 + arow) * 256 + ag * 8);
        float4 v0 = p[0], v1 = p[1];
        af[0] = v0.x; af[1] = v0.y; af[2] = v0.z; af[3] = v0.w;
        af[4] = v1.x; af[5] = v1.y; af[6] = v1.z; af[7] = v1.w;
        if (BN) {
            int kk = ag * 8;
#pragma unroll
            for (int i = 0; i < 8; i++)
                af[i] = fmaxf(fmaf(af[i], ascale[kk + i], ashift[kk + i]), 0.f);
        }
        size_t ws = (size_t)wrow * 256 + wg * 8;
#pragma unroll
        for (int j = 0; j < 4; j++)
            cpasync16(stg0 + STG_W + w_sts + j * 4096u, Wh + ws + (size_t)j * 64 * 256);
        cpcommit();
        uint4 hv, lv;
        __half2* hp = (__half2*)&hv;
        __half2* lp = (__half2*)&lv;
#pragma unroll
        for (int i = 0; i < 4; i++) {
            __half h0 = __float2half(af[2 * i]);
            __half h1 = __float2half(af[2 * i + 1]);
            hp[i].x = h0; hp[i].y = h1;
            lp[i].x = __float2half(af[2 * i]     - __half2float(h0));
            lp[i].y = __float2half(af[2 * i + 1] - __half2float(h1));
        }
        STS128(stg0 + a_sts, hv);
        STS128(stg0 + STG_ALO + a_sts, lv);
        cpwait0();
    }
    __syncthreads();

    // ===== mainloop: 8 chunks of k32 =====
    for (int c = 0; c < 8; c++) {
        const uint32_t stgs = stg0 + (uint32_t)(c & 1) * STG_SIZE;
        const uint32_t stgn = stg0 + (uint32_t)((c + 1) & 1) * STG_SIZE;

        if (c < 7) {
            const float4* p = (const float4*)(A + (r0 + arow) * 256 + (c + 1) * 32 + ag * 8);
            float4 v0 = p[0], v1 = p[1];
            af[0] = v0.x; af[1] = v0.y; af[2] = v0.z; af[3] = v0.w;
            af[4] = v1.x; af[5] = v1.y; af[6] = v1.z; af[7] = v1.w;
            if (BN) {
                int kk = (c + 1) * 32 + ag * 8;
#pragma unroll
                for (int i = 0; i < 8; i++)
                    af[i] = fmaxf(fmaf(af[i], ascale[kk + i], ashift[kk + i]), 0.f);
            }
            size_t ws = (size_t)wrow * 256 + (c + 1) * 32 + wg * 8;
#pragma unroll
            for (int j = 0; j < 4; j++)
                cpasync16(stgn + STG_W + w_sts + j * 4096u, Wh + ws + (size_t)j * 64 * 256);
            cpcommit();
        }

        // ---- compute chunk c ----
#pragma unroll
        for (int ks = 0; ks < 2; ks++) {
            uint32_t ah[2][4], al[2][4], bb[4];
            const uint32_t agoff = (uint32_t)(((ks * 2 + a_gl) ^ sa) << 4);
            ldsm4(ah[0], stgs + a_off0 + agoff);
            ldsm4(ah[1], stgs + a_off0 + 1024 + agoff);
            ldsm4(al[0], stgs + STG_ALO + a_off0 + agoff);
            ldsm4(al[1], stgs + STG_ALO + a_off0 + 1024 + agoff);
            const uint32_t bgoff = (uint32_t)(((ks * 2 + b_gl) ^ sbz) << 4);
#pragma unroll
            for (int n2 = 0; n2 < 4; n2++) {
                const uint32_t brow = b_off0 + (uint32_t)(n2 * 1024);
                ldsm4(bb, stgs + STG_W + brow + bgoff);
                mma16816(acc[0][n2 * 2],     ah[0], bb);
                mma16816(acc[0][n2 * 2 + 1], ah[0], bb + 2);
                mma16816(acc[1][n2 * 2],     ah[1], bb);
                mma16816(acc[1][n2 * 2 + 1], ah[1], bb + 2);
                mma16816(acc[0][n2 * 2],     al[0], bb);
                mma16816(acc[0][n2 * 2 + 1], al[0], bb + 2);
                mma16816(acc[1][n2 * 2],     al[1], bb);
                mma16816(acc[1][n2 * 2 + 1], al[1], bb + 2);
            }
        }

        if (c < 7) {
            uint4 hv, lv;
            __half2* hp = (__half2*)&hv;
            __half2* lp = (__half2*)&lv;
#pragma unroll
            for (int i = 0; i < 4; i++) {
                __half h0 = __float2half(af[2 * i]);
                __half h1 = __float2half(af[2 * i + 1]);
                hp[i].x = h0; hp[i].y = h1;
                lp[i].x = __float2half(af[2 * i]     - __half2float(h0));
                lp[i].y = __float2half(af[2 * i + 1] - __half2float(h1));
            }
            STS128(stgn + a_sts, hv);
            STS128(stgn + STG_ALO + a_sts, lv);
            cpwait0();
            __syncthreads();
        }
    }

    // ===== epilogue =====
    const int erow = wr * 32 + (l >> 2);
#pragma unroll
    for (int nt = 0; nt < 8; nt++) {
        const int col = wc * 64 + nt * 8 + (l & 3) * 2;
        const float2 bb2 = *(const float2*)(bias + col);
        float s0 = 0.f, s1 = 0.f, q0 = 0.f, q1 = 0.f;
#pragma unroll
        for (int mt = 0; mt < 2; mt++) {
            const size_t row = r0 + erow + mt * 16;
            float v0 = acc[mt][nt][0] + bb2.x;
            float v1 = acc[mt][nt][1] + bb2.y;
            float v2 = acc[mt][nt][2] + bb2.x;
            float v3 = acc[mt][nt][3] + bb2.y;
            *(float2*)(C + row * 256 + col)       = make_float2(v0, v1);
            *(float2*)(C + (row + 8) * 256 + col) = make_float2(v2, v3);
            if (SUB) {
                float2 qa = *(const float2*)(Qsub + row * 256 + col);
                float2 qb = *(const float2*)(Qsub + (row + 8) * 256 + col);
                float w0 = v0 - qa.x, w1 = v1 - qa.y;
                float w2 = v2 - qb.x, w3 = v3 - qb.y;
                *(float2*)(Wout + row * 256 + col)       = make_float2(w0, w1);
                *(float2*)(Wout + (row + 8) * 256 + col) = make_float2(w2, w3);
                s0 += w0 + w2; s1 += w1 + w3;
                q0 += w0 * w0 + w2 * w2; q1 += w1 * w1 + w3 * w3;
            } else if (STATS) {
                s0 += v0 + v2; s1 += v1 + v3;
                q0 += v0 * v0 + v2 * v2; q1 += v1 * v1 + v3 * v3;
            }
        }
        if (STATS) {
            float* ss = (float*)smem;
            atomicAdd(ss + col,           s0);
            atomicAdd(ss + col + 1,       s1);
            atomicAdd(ss + 256 + col,     q0);
            atomicAdd(ss + 256 + col + 1, q1);
        }
    }

    if (STATS) {
        __syncthreads();
        atomicAdd(gsum + t, ((float*)smem)[t]);
        atomicAdd(gsq  + t, ((float*)smem)[256 + t]);
    }
}

// ---- wrappers ----
__global__ __launch_bounds__(256, 2)
void gemm_plain(const float* A, const __half* Wh, const float* bias, float* C)
{
    gemm_core<false, false, false>(A, Wh, bias, nullptr, nullptr, C,
                                   nullptr, nullptr, nullptr, nullptr);
}
__global__ __launch_bounds__(256, 2)
void gemm_kv(const float* Ka, const __half* KWh, const float* kb, float* Kd,
             const float* Va, const __half* VWh, const float* vb, float* Vd,
             const float* Qd, float* Wout, float* gsum, float* gsq)
{
    if (blockIdx.y == 0)
        gemm_core<false, true, true>(Ka, KWh, kb, nullptr, nullptr, Kd,
                                     Qd, Wout, gsum, gsq);
    else
        gemm_core<false, false, false>(Va, VWh, vb, nullptr, nullptr, Vd,
                                       nullptr, nullptr, nullptr, nullptr);
}
__global__ __launch_bounds__(256, 2)
void gemm_bn_stats(const float* A, const __half* Wh, const float* bias,
                   const float* ascale, const float* ashift,
                   float* C, float* gsum, float* gsq)
{
    gemm_core<true, false, true>(A, Wh, bias, ascale, ashift, C,
                                 nullptr, nullptr, gsum, gsq);
}
__global__ __launch_bounds__(256, 2)
void gemm_bn(const float* A, const __half* Wh, const float* bias,
             const float* ascale, const float* ashift, float* C)
{
    gemm_core<true, false, false>(A, Wh, bias, ascale, ashift, C,
                                  nullptr, nullptr, nullptr, nullptr);
}

// ---------------------------------------------------------------------------
__global__ void wconv(const float* __restrict__ w0, const float* __restrict__ w1,
                      const float* __restrict__ w2, const float* __restrict__ w3,
                      const float* __restrict__ w4, __half* __restrict__ out)
{
    size_t i = (size_t)blockIdx.x * 256 + threadIdx.x;
    size_t a = i >> 18, r = i & 262143;
    const float* s = (a == 0) ? w0 : (a == 1) ? w1 : (a == 2) ? w2 : (a == 3) ? w3 : w4;
    out[i] = __float2half(s[r]);
}

__global__ void zerok(float* a, float* b)
{
    a[threadIdx.x] = 0.f;
    b[threadIdx.x] = 0.f;
}

__global__ void bnfinal(const float* __restrict__ s, const float* __restrict__ sq,
                        const float* __restrict__ gamma, const float* __restrict__ beta,
                        float* __restrict__ scale, float* __restrict__ shift)
{
    int c = threadIdx.x;
    const float inv = 1.f / 65536.f;
    float m = s[c] * inv;
    float v = sq[c] * inv - m * m;
    float r = rsqrtf(v + 1e-5f);
    float sc = r * gamma[c];
    scale[c] = sc;
    shift[c] = beta[c] - m * sc;
}

// Online softmax over S fused with weighted V-sum (16-way split over S)
__global__ void smax_part(const float* __restrict__ W3, const float* __restrict__ V,
                          float* __restrict__ pm, float* __restrict__ pz,
                          float* __restrict__ pa)
{
    int b = blockIdx.x, ch = blockIdx.y, d = threadIdx.x;
    float m = -1e30f, Z = 0.f, acc = 0.f;
#pragma unroll 4
    for (int j = 0; j < 128; j++) {
        int s_ = ch * 128 + j;
        size_t idx = ((size_t)(s_ * 32 + b)) * 256 + d;
        float w = W3[idx];
        float v = V[idx];
        float nm = fmaxf(m, w);
        float e0 = __expf(m - nm);
        float e1 = __expf(w - nm);
        Z = Z * e0 + e1;
        acc = fmaf(v, e1, acc * e0);
        m = nm;
    }
    int o = (ch * 32 + b) * 256 + d;
    pm[o] = m; pz[o] = Z; pa[o] = acc;
}

__global__ void smax_comb(const float* __restrict__ pm, const float* __restrict__ pz,
                          const float* __restrict__ pa, float* __restrict__ xcat,
                          int head)
{
    int b = blockIdx.x, d = threadIdx.x;
    float m = -1e30f, Z = 0.f, acc = 0.f;
#pragma unroll
    for (int ch = 0; ch < 16; ch++) {
        int o = (ch * 32 + b) * 256 + d;
        float cm = pm[o];
        float nm = fmaxf(m, cm);
        float e0 = __expf(m - nm);
        float e1 = __expf(cm - nm);
        Z = Z * e0 + pz[o] * e1;
        acc = acc * e0 + pa[o] * e1;
        m = nm;
    }
    xcat[b * 1024 + head * 256 + d] = acc / Z;
}

__global__ void mlp_k(const float* __restrict__ X, const float* __restrict__ Wm,
                      const float* __restrict__ bias, float* __restrict__ Y,
                      int Kdim, int do_relu)
{
    __shared__ float sx[1024];
    int b = blockIdx.x, c = threadIdx.x;
    for (int t = c; t < Kdim; t += 256) sx[t] = X[b * Kdim + t];
    __syncthreads();
    float s = 0.f;
#pragma unroll 4
    for (int t = 0; t < Kdim; t++) s = fmaf(sx[t], Wm[c * Kdim + t], s);
    s += bias[c];
    if (do_relu) s = fmaxf(s, 0.f);
    Y[b * 256 + c] = s;
}

// ---------------------------------------------------------------------------
extern "C" void kernel_launch(void* const* d_in, const int* in_sizes, int n_in,
                              void* d_out, int out_size)
{
    float* pool = nullptr;
    cudaGetSymbolAddress((void**)&pool, g_pool);

    cudaFuncSetAttribute(gemm_plain,    cudaFuncAttributeMaxDynamicSharedMemorySize, GEMM_SMEM);
    cudaFuncSetAttribute(gemm_kv,       cudaFuncAttributeMaxDynamicSharedMemorySize, GEMM_SMEM);
    cudaFuncSetAttribute(gemm_bn_stats, cudaFuncAttributeMaxDynamicSharedMemorySize, GEMM_SMEM);
    cudaFuncSetAttribute(gemm_bn,       cudaFuncAttributeMaxDynamicSharedMemorySize, GEMM_SMEM);

    const float* q   = (const float*)d_in[0];
    const float* k   = (const float*)d_in[1];
    const float* v   = (const float*)d_in[2];
    const float* wq  = (const float*)d_in[3];
    const float* bq  = (const float*)d_in[4];
    const float* wk  = (const float*)d_in[5];
    const float* bk  = (const float*)d_in[6];
    const float* wv  = (const float*)d_in[7];
    const float* bv  = (const float*)d_in[8];
    const float* g1  = (const float*)d_in[9];
    const float* be1 = (const float*)d_in[10];
    const float* wl1 = (const float*)d_in[11];
    const float* bl1 = (const float*)d_in[12];
    const float* g2  = (const float*)d_in[13];
    const float* be2 = (const float*)d_in[14];
    const float* wl2 = (const float*)d_in[15];
    const float* bl2 = (const float*)d_in[16];
    const float* mw0 = (const float*)d_in[17];
    const float* mb0 = (const float*)d_in[18];
    const float* mw1 = (const float*)d_in[19];
    const float* mb1 = (const float*)d_in[20];
    const float* mw2 = (const float*)d_in[21];
    const float* mb2 = (const float*)d_in[22];

    float* Qb[2] = {pool + 0 * MD_, pool + 1 * MD_};
    float* Kb[2] = {pool + 2 * MD_, pool + 3 * MD_};
    float* Vb[2] = {pool + 4 * MD_, pool + 5 * MD_};
    float* W     = pool + 6 * MD_;
    float* W2    = pool + 7 * MD_;
    float* ssum  = pool + O_SSUM;
    float* ssq   = pool + O_SSQ;
    float* scale = pool + O_SCALE;
    float* shift = pool + O_SHIFT;
    float* pm    = pool + O_PM;
    float* pz    = pool + O_PZ;
    float* pa    = pool + O_PA;
    float* xcat  = pool + O_XCAT;
    float* h0    = pool + O_H0;
    float* h1    = pool + O_H1;
    __half* wf = (__half*)(pool + O_WF16);

    // convert all 20 weight matrices to fp16  (arr order: wq,wk,wv,wl1,wl2)
    wconv<<<5120, 256>>>(wq, wk, wv, wl1, wl2, wf);

    const int NT = MROWS / 64;   // 1024 row tiles

    for (int i = 0; i < 4; i++) {
        const float* Qs = i ? Qb[(i - 1) & 1] : q;
        const float* Ks = i ? Kb[(i - 1) & 1] : k;
        const float* Vs = i ? Vb[(i - 1) & 1] : v;
        float* Qd = Qb[i & 1];
        float* Kd = Kb[i & 1];
        float* Vd = Vb[i & 1];

        const __half* whq = wf + (0 * 4 + i) * 65536;
        const __half* whk = wf + (1 * 4 + i) * 65536;
        const __half* whv = wf + (2 * 4 + i) * 65536;
        const __half* wh1 = wf + (3 * 4 + i) * 65536;
        const __half* wh2 = wf + (4 * 4 + i) * 65536;

        gemm_plain<<<NT, 256, GEMM_SMEM>>>(Qs, whq, bq + i * 256, Qd);

        zerok<<<1, 256>>>(ssum, ssq);
        gemm_kv<<<dim3(NT, 2), 256, GEMM_SMEM>>>(
            Ks, whk, bk + i * 256, Kd,
            Vs, whv, bv + i * 256, Vd,
            Qd, W, ssum, ssq);
        bnfinal<<<1, 256>>>(ssum, ssq, g1 + i * 256, be1 + i * 256, scale, shift);

        zerok<<<1, 256>>>(ssum, ssq);
        gemm_bn_stats<<<NT, 256, GEMM_SMEM>>>(W, wh1, bl1 + i * 256,
                                              scale, shift, W2, ssum, ssq);
        bnfinal<<<1, 256>>>(ssum, ssq, g2 + i * 256, be2 + i * 256, scale, shift);

        gemm_bn<<<NT, 256, GEMM_SMEM>>>(W2, wh2, bl2 + i * 256, scale, shift, W);

        smax_part<<<dim3(32, 16), 256>>>(W, Vd, pm, pz, pa);
        smax_comb<<<32, 256>>>(pm, pz, pa, xcat, i);
    }

    mlp_k<<<32, 256>>>(xcat, mw0, mb0, h0, 1024, 1);
    mlp_k<<<32, 256>>>(h0, mw1, mb1, h1, 256, 1);
    mlp_k<<<32, 256>>>(h1, mw2, mb2, (float*)d_out, 256, 0);
}